// round 3
// baseline (speedup 1.0000x reference)
#include <cuda_runtime.h>

#define NIMG 8
#define IMG  512
#define PR   514
#define S    520
#define COFF 4

__device__ float g_min_a[NIMG * PR * S];
__device__ float g_min_b[NIMG * PR * S];
__device__ float g_max_a[NIMG * PR * S];
__device__ float g_max_b[NIMG * PR * S];

struct HeadConsts {
    float A2[32][18][2];   // [j][k<9: Amin taps, k>=9: Amax taps][dup pair]
    float cb2[32][2];
    float w2[32];
    float Amin[32][9];
    float Amax[32][9];
    float Bsum[32][9];
    float b1[32];
    float b2;
};
__device__ HeadConsts HC;

__device__ __forceinline__ float fmin3(float a, float b, float c) { return fminf(a, fminf(b, c)); }
__device__ __forceinline__ float fmax3(float a, float b, float c) { return fmaxf(a, fmaxf(b, c)); }

__device__ __forceinline__ unsigned long long pk2(float lo, float hi) {
    unsigned long long r;
    asm("mov.b64 %0, {%1, %2};" : "=l"(r) : "f"(lo), "f"(hi));
    return r;
}
__device__ __forceinline__ void upk2(unsigned long long v, float& lo, float& hi) {
    asm("mov.b64 {%0, %1}, %2;" : "=f"(lo), "=f"(hi) : "l"(v));
}
__device__ __forceinline__ unsigned long long fma2(unsigned long long a, unsigned long long b,
                                                   unsigned long long c) {
    unsigned long long d;
    asm("fma.rn.f32x2 %0, %1, %2, %3;" : "=l"(d) : "l"(a), "l"(b), "l"(c));
    return d;
}

// ---- fold weights ----------------------------------------------------------
__global__ void prep_kernel(const float* __restrict__ w0, const float* __restrict__ b0,
                            const float* __restrict__ w1, const float* __restrict__ b1,
                            const float* __restrict__ w2, const float* __restrict__ b2) {
    int id = threadIdx.x;
    if (id < 288) {
        int j = id / 9, t = id % 9;
        float amin = 0.f, amax = 0.f, bs = 0.f;
        for (int c = 0; c < 8; c++) {
            float w = w1[j * 72 + c * 9 + t];
            float w0c = w0[c];
            if (w0c >= 0.f) amin += w * w0c; else amax += w * w0c;
            bs += w * (65536.f * b0[c]);
        }
        HC.Amin[j][t] = amin; HC.Amax[j][t] = amax; HC.Bsum[j][t] = bs;
        HC.A2[j][t][0] = amin;     HC.A2[j][t][1] = amin;
        HC.A2[j][9 + t][0] = amax; HC.A2[j][9 + t][1] = amax;
    }
    if (id < 32) {
        int j = id;
        float cb = b1[j];
        for (int c = 0; c < 8; c++) {
            float bc = 65536.f * b0[c];
            for (int t = 0; t < 9; t++) cb += w1[j * 72 + c * 9 + t] * bc;
        }
        HC.cb2[j][0] = cb; HC.cb2[j][1] = cb;
        HC.w2[j] = w2[j];
        HC.b1[j] = b1[j];
    }
    if (id == 0) HC.b2 = b2[0];
}

// ---- halo init: +inf for min field, -inf for max field ---------------------
__global__ void halo_init_kernel() {
    int idx = blockIdx.x * blockDim.x + threadIdx.x;
    if (idx >= NIMG * PR * S) return;
    int col = idx % S;
    int row = (idx / S) % PR;
    if (row == 0 || row == PR - 1 || col < COFF || col >= COFF + IMG) {
        float pinf = __int_as_float(0x7F800000);
        g_min_a[idx] = pinf;  g_min_b[idx] = pinf;
        g_max_a[idx] = -pinf; g_max_b[idx] = -pinf;
    }
}

// ---- iteration 0: from x (unpadded) into buffers A -------------------------
__global__ __launch_bounds__(256) void iter0_kernel(const float* __restrict__ x) {
    const int lane = threadIdx.x;
    const int r = blockIdx.y * 8 + threadIdx.y;
    const int c = blockIdx.x * 128 + lane * 4;
    const int img = blockIdx.z;
    const float* xi = x + (size_t)img * IMG * IMG;
    const float FINF = __int_as_float(0x7F800000);

    float4 hmn[3], hmx[3];
    float4 center = make_float4(0.f, 0.f, 0.f, 0.f);
#pragma unroll
    for (int d = 0; d < 3; d++) {
        int rr = r + d - 1;
        if (rr < 0 || rr >= IMG) {
            hmn[d] = make_float4(FINF, FINF, FINF, FINF);
            hmx[d] = make_float4(-FINF, -FINF, -FINF, -FINF);
            continue;
        }
        const float* rp = xi + (size_t)rr * IMG;
        float4 v = *(const float4*)(rp + c);
        if (d == 1) center = v;
        float left  = __shfl_up_sync(0xffffffffu, v.w, 1);
        float right = __shfl_down_sync(0xffffffffu, v.x, 1);
        bool lv = true, rv = true;
        if (lane == 0)  { if (c == 0) lv = false; else left = rp[c - 1]; }
        if (lane == 31) { if (c + 4 >= IMG) rv = false; else right = rp[c + 4]; }
        float lmn = lv ? left : FINF,  rmn = rv ? right : FINF;
        float lmx = lv ? left : -FINF, rmx = rv ? right : -FINF;
        hmn[d].x = fmin3(lmn, v.x, v.y); hmn[d].y = fmin3(v.x, v.y, v.z);
        hmn[d].z = fmin3(v.y, v.z, v.w); hmn[d].w = fmin3(v.z, v.w, rmn);
        hmx[d].x = fmax3(lmx, v.x, v.y); hmx[d].y = fmax3(v.x, v.y, v.z);
        hmx[d].z = fmax3(v.y, v.z, v.w); hmx[d].w = fmax3(v.z, v.w, rmx);
    }
    float4 omn, omx;
    omn.x = center.x + fmin3(hmn[0].x, hmn[1].x, hmn[2].x);
    omn.y = center.y + fmin3(hmn[0].y, hmn[1].y, hmn[2].y);
    omn.z = center.z + fmin3(hmn[0].z, hmn[1].z, hmn[2].z);
    omn.w = center.w + fmin3(hmn[0].w, hmn[1].w, hmn[2].w);
    omx.x = center.x + fmax3(hmx[0].x, hmx[1].x, hmx[2].x);
    omx.y = center.y + fmax3(hmx[0].y, hmx[1].y, hmx[2].y);
    omx.z = center.z + fmax3(hmx[0].z, hmx[1].z, hmx[2].z);
    omx.w = center.w + fmax3(hmx[0].w, hmx[1].w, hmx[2].w);

    size_t base = (size_t)img * PR * S + (size_t)(r + 1) * S + COFF + c;
    *(float4*)(g_min_a + base) = omn;
    *(float4*)(g_max_a + base) = omx;
}

// ---- steady-state iteration: branch-free via inf halo ----------------------
template <bool IS_MIN>
__device__ __forceinline__ float4 hpool_pad(const float* __restrict__ rp, int c, float4 v, int lane) {
    float left  = __shfl_up_sync(0xffffffffu, v.w, 1);
    float right = __shfl_down_sync(0xffffffffu, v.x, 1);
    if (lane == 0)  left  = rp[c - 1];
    if (lane == 31) right = rp[c + 4];
    float4 h;
    if (IS_MIN) {
        h.x = fmin3(left, v.x, v.y); h.y = fmin3(v.x, v.y, v.z);
        h.z = fmin3(v.y, v.z, v.w);  h.w = fmin3(v.z, v.w, right);
    } else {
        h.x = fmax3(left, v.x, v.y); h.y = fmax3(v.x, v.y, v.z);
        h.z = fmax3(v.y, v.z, v.w);  h.w = fmax3(v.z, v.w, right);
    }
    return h;
}

template <bool IS_MIN>
__device__ __forceinline__ void iter_field(const float* __restrict__ src, float* __restrict__ dst,
                                           size_t ib, int r, int c, int lane) {
    const float* r0 = src + ib + (size_t)r * S + COFF;
    const float* r1 = r0 + S;
    const float* r2 = r1 + S;
    float4 a = *(const float4*)(r0 + c);
    float4 b = *(const float4*)(r1 + c);
    float4 d = *(const float4*)(r2 + c);
    float4 h0 = hpool_pad<IS_MIN>(r0, c, a, lane);
    float4 h1 = hpool_pad<IS_MIN>(r1, c, b, lane);
    float4 h2 = hpool_pad<IS_MIN>(r2, c, d, lane);
    float4 o;
    if (IS_MIN) {
        o.x = b.x + fmin3(h0.x, h1.x, h2.x); o.y = b.y + fmin3(h0.y, h1.y, h2.y);
        o.z = b.z + fmin3(h0.z, h1.z, h2.z); o.w = b.w + fmin3(h0.w, h1.w, h2.w);
    } else {
        o.x = b.x + fmax3(h0.x, h1.x, h2.x); o.y = b.y + fmax3(h0.y, h1.y, h2.y);
        o.z = b.z + fmax3(h0.z, h1.z, h2.z); o.w = b.w + fmax3(h0.w, h1.w, h2.w);
    }
    *(float4*)(dst + ib + (size_t)(r + 1) * S + COFF + c) = o;
}

__global__ __launch_bounds__(256) void iter_kernel(int srcIsB) {
    const int lane = threadIdx.x;
    const int r = blockIdx.y * 8 + threadIdx.y;
    const int c = blockIdx.x * 128 + lane * 4;
    const size_t ib = (size_t)blockIdx.z * PR * S;
    const float* smin = srcIsB ? g_min_b : g_min_a;
    float*       dmin = srcIsB ? g_min_a : g_min_b;
    const float* smax = srcIsB ? g_max_b : g_max_a;
    float*       dmax = srcIsB ? g_max_a : g_max_b;
    iter_field<true>(smin, dmin, ib, r, c, lane);
    iter_field<false>(smax, dmax, ib, r, c, lane);
}

// ---- head fast path: 2x4 pixels/thread, packed fma.rn.f32x2 ----------------
__global__ __launch_bounds__(128) void head_main_kernel(float* __restrict__ out) {
    __shared__ unsigned long long A2s[32][18];
    __shared__ unsigned long long cb2s[32];
    __shared__ float w2s[32];
    const int tid = threadIdx.y * 32 + threadIdx.x;
    {
        const unsigned long long* A2g = (const unsigned long long*)(&HC.A2[0][0][0]);
        for (int i = tid; i < 32 * 18; i += 128) ((unsigned long long*)A2s)[i] = A2g[i];
        if (tid < 32) {
            cb2s[tid] = ((const unsigned long long*)HC.cb2)[tid];
            w2s[tid] = HC.w2[tid];
        }
    }
    __syncthreads();

    const int img = blockIdx.z;
    const int x0 = (blockIdx.x * 32 + threadIdx.x) * 2;
    const int y0 = (blockIdx.y * 4 + threadIdx.y) * 4;
    const float* gm = g_min_b + (size_t)img * PR * S;
    const float* gx = g_max_b + (size_t)img * PR * S;

    unsigned long long tmin[6][3], tmax[6][3];
#pragma unroll
    for (int rr = 0; rr < 6; rr++) {
        const float* pm = gm + (size_t)(y0 + rr) * S + COFF + x0;
        float2 L = *(const float2*)(pm - 2);
        float2 M = *(const float2*)(pm);
        float2 R = *(const float2*)(pm + 2);
        tmin[rr][0] = pk2(L.y, M.x); tmin[rr][1] = pk2(M.x, M.y); tmin[rr][2] = pk2(M.y, R.x);
        const float* px = gx + (size_t)(y0 + rr) * S + COFF + x0;
        L = *(const float2*)(px - 2);
        M = *(const float2*)(px);
        R = *(const float2*)(px + 2);
        tmax[rr][0] = pk2(L.y, M.x); tmax[rr][1] = pk2(M.x, M.y); tmax[rr][2] = pk2(M.y, R.x);
    }

    float accx[4] = {0.f, 0.f, 0.f, 0.f};
    float accy[4] = {0.f, 0.f, 0.f, 0.f};
#pragma unroll 2
    for (int j = 0; j < 32; j++) {
        unsigned long long u0 = cb2s[j], u1 = u0, u2 = u0, u3 = u0;
#pragma unroll
        for (int k = 0; k < 9; k++) {
            const int kh = k / 3, kw = k % 3;
            unsigned long long a = A2s[j][k];
            u0 = fma2(a, tmin[0 + kh][kw], u0);
            u1 = fma2(a, tmin[1 + kh][kw], u1);
            u2 = fma2(a, tmin[2 + kh][kw], u2);
            u3 = fma2(a, tmin[3 + kh][kw], u3);
        }
#pragma unroll
        for (int k = 0; k < 9; k++) {
            const int kh = k / 3, kw = k % 3;
            unsigned long long a = A2s[j][9 + k];
            u0 = fma2(a, tmax[0 + kh][kw], u0);
            u1 = fma2(a, tmax[1 + kh][kw], u1);
            u2 = fma2(a, tmax[2 + kh][kw], u2);
            u3 = fma2(a, tmax[3 + kh][kw], u3);
        }
        float w = w2s[j], lo, hi;
        upk2(u0, lo, hi);
        accx[0] = fmaf(w, fmaxf(lo, 0.f), accx[0]); accy[0] = fmaf(w, fmaxf(hi, 0.f), accy[0]);
        upk2(u1, lo, hi);
        accx[1] = fmaf(w, fmaxf(lo, 0.f), accx[1]); accy[1] = fmaf(w, fmaxf(hi, 0.f), accy[1]);
        upk2(u2, lo, hi);
        accx[2] = fmaf(w, fmaxf(lo, 0.f), accx[2]); accy[2] = fmaf(w, fmaxf(hi, 0.f), accy[2]);
        upk2(u3, lo, hi);
        accx[3] = fmaf(w, fmaxf(lo, 0.f), accx[3]); accy[3] = fmaf(w, fmaxf(hi, 0.f), accy[3]);
    }

    const float b2v = HC.b2;
#pragma unroll
    for (int i = 0; i < 4; i++) {
        float2 o;
        o.x = b2v + accx[i];
        o.y = b2v + accy[i];
        *(float2*)(out + (size_t)img * IMG * IMG + (size_t)(y0 + i) * IMG + x0) = o;
    }
}

// ---- head border: exact tap-gated recompute for the 1-pixel frame ----------
__global__ void head_border_kernel(float* __restrict__ out) {
    const int img = blockIdx.y;
    const int bi = blockIdx.x * blockDim.x + threadIdx.x;  // 0..2043
    if (bi >= 2044) return;
    int x, y;
    if (bi < 512)        { y = 0;   x = bi; }
    else if (bi < 1024)  { y = 511; x = bi - 512; }
    else if (bi < 1534)  { x = 0;   y = bi - 1024 + 1; }
    else                 { x = 511; y = bi - 1534 + 1; }

    const float* gm = g_min_b + (size_t)img * PR * S;
    const float* gx = g_max_b + (size_t)img * PR * S;

    float vmn[9], vmx[9];
    bool valid[9];
#pragma unroll
    for (int k = 0; k < 9; k++) {
        int ty = y + k / 3 - 1, tx = x + k % 3 - 1;
        valid[k] = (ty >= 0 && ty < IMG && tx >= 0 && tx < IMG);
        size_t off = (size_t)(ty + 1) * S + COFF + tx;
        vmn[k] = valid[k] ? gm[off] : 0.f;
        vmx[k] = valid[k] ? gx[off] : 0.f;
    }
    float acc = 0.f;
    for (int j = 0; j < 32; j++) {
        float u = HC.b1[j];
#pragma unroll
        for (int k = 0; k < 9; k++) {
            if (valid[k])
                u += HC.Amin[j][k] * vmn[k] + HC.Amax[j][k] * vmx[k] + HC.Bsum[j][k];
        }
        acc = fmaf(HC.w2[j], fmaxf(u, 0.f), acc);
    }
    out[(size_t)img * IMG * IMG + (size_t)y * IMG + x] = HC.b2 + acc;
}

// ---------------------------------------------------------------------------
extern "C" void kernel_launch(void* const* d_in, const int* in_sizes, int n_in,
                              void* d_out, int out_size) {
    const float* x  = (const float*)d_in[0];
    const float* w0 = (const float*)d_in[1];
    const float* b0 = (const float*)d_in[2];
    const float* w1 = (const float*)d_in[3];
    const float* b1 = (const float*)d_in[4];
    const float* w2 = (const float*)d_in[5];
    const float* b2 = (const float*)d_in[6];
    float* out = (float*)d_out;

    prep_kernel<<<1, 288>>>(w0, b0, w1, b1, w2, b2);

    int tot = NIMG * PR * S;
    halo_init_kernel<<<(tot + 255) / 256, 256>>>();

    dim3 blk(32, 8);
    dim3 grd(IMG / 128, IMG / 8, NIMG);
    iter0_kernel<<<grd, blk>>>(x);
    for (int i = 1; i < 16; i++)
        iter_kernel<<<grd, blk>>>((i % 2) == 0 ? 1 : 0);

    dim3 hblk(32, 4);
    dim3 hgrd(IMG / 64, IMG / 16, NIMG);
    head_main_kernel<<<hgrd, hblk>>>(out);

    head_border_kernel<<<dim3(16, NIMG), 128>>>(out);
}

// round 4
// speedup vs baseline: 1.6035x; 1.6035x over previous
#include <cuda_runtime.h>

#define NIMG 8
#define IMG  512
#define NPIX (IMG * IMG)

// Unpadded ping-pong field buffers.
__device__ float g_min_a[NIMG * NPIX];
__device__ float g_min_b[NIMG * NPIX];
__device__ float g_max_a[NIMG * NPIX];
__device__ float g_max_b[NIMG * NPIX];

struct HeadConsts {
    float A2[32][18][2];   // [j][k<9: Amin taps, k>=9: Amax taps][dup pair]
    float cb2[32][2];
    float w2[32];
    float Amin[32][9];
    float Amax[32][9];
    float Bsum[32][9];
    float b1[32];
    float b2;
};
__device__ HeadConsts HC;

__device__ __forceinline__ float fmin3(float a, float b, float c) { return fminf(a, fminf(b, c)); }
__device__ __forceinline__ float fmax3(float a, float b, float c) { return fmaxf(a, fmaxf(b, c)); }

__device__ __forceinline__ unsigned long long pk2(float lo, float hi) {
    unsigned long long r;
    asm("mov.b64 %0, {%1, %2};" : "=l"(r) : "f"(lo), "f"(hi));
    return r;
}
__device__ __forceinline__ void upk2(unsigned long long v, float& lo, float& hi) {
    asm("mov.b64 {%0, %1}, %2;" : "=f"(lo), "=f"(hi) : "l"(v));
}
__device__ __forceinline__ unsigned long long fma2(unsigned long long a, unsigned long long b,
                                                   unsigned long long c) {
    unsigned long long d;
    asm("fma.rn.f32x2 %0, %1, %2, %3;" : "=l"(d) : "l"(a), "l"(b), "l"(c));
    return d;
}

// ---- fold weights ----------------------------------------------------------
__global__ void prep_kernel(const float* __restrict__ w0, const float* __restrict__ b0,
                            const float* __restrict__ w1, const float* __restrict__ b1,
                            const float* __restrict__ w2, const float* __restrict__ b2) {
    int id = threadIdx.x;
    if (id < 288) {
        int j = id / 9, t = id % 9;
        float amin = 0.f, amax = 0.f, bs = 0.f;
        for (int c = 0; c < 8; c++) {
            float w = w1[j * 72 + c * 9 + t];
            float w0c = w0[c];
            if (w0c >= 0.f) amin += w * w0c; else amax += w * w0c;
            bs += w * (65536.f * b0[c]);
        }
        HC.Amin[j][t] = amin; HC.Amax[j][t] = amax; HC.Bsum[j][t] = bs;
        HC.A2[j][t][0] = amin;     HC.A2[j][t][1] = amin;
        HC.A2[j][9 + t][0] = amax; HC.A2[j][9 + t][1] = amax;
    }
    if (id < 32) {
        int j = id;
        float cb = b1[j];
        for (int c = 0; c < 8; c++) {
            float bc = 65536.f * b0[c];
            for (int t = 0; t < 9; t++) cb += w1[j * 72 + c * 9 + t] * bc;
        }
        HC.cb2[j][0] = cb; HC.cb2[j][1] = cb;
        HC.w2[j] = w2[j];
        HC.b1[j] = b1[j];
    }
    if (id == 0) HC.b2 = b2[0];
}

// ---- fused 4-iteration round, all data in registers ------------------------
// CTA: 128 threads = 4 warps spanning the full 512-col width.
// Each thread: 16 rows x 4 cols in registers; outputs middle 8 rows after
// 4 pooling iterations. Warp-edge columns exchanged via smem (double-buffered).

template <bool IS_MIN>
__device__ __forceinline__ float4 hrow(float4 v, int r, int p, int warp, int lane,
                                       const float* eL, const float* eR, float BND) {
    float left  = __shfl_up_sync(0xffffffffu, v.w, 1);
    float right = __shfl_down_sync(0xffffffffu, v.x, 1);
    if (lane == 0)  left  = (warp == 0) ? BND : eR[((p * 4) + warp - 1) * 16 + r];
    if (lane == 31) right = (warp == 3) ? BND : eL[((p * 4) + warp + 1) * 16 + r];
    float4 h;
    if (IS_MIN) {
        h.x = fmin3(left, v.x, v.y); h.y = fmin3(v.x, v.y, v.z);
        h.z = fmin3(v.y, v.z, v.w);  h.w = fmin3(v.z, v.w, right);
    } else {
        h.x = fmax3(left, v.x, v.y); h.y = fmax3(v.x, v.y, v.z);
        h.z = fmax3(v.y, v.z, v.w);  h.w = fmax3(v.z, v.w, right);
    }
    return h;
}

template <bool IS_MIN>
__device__ __forceinline__ void do_round(const float* __restrict__ src, float* __restrict__ dst,
                                         float* eL, float* eR) {
    const int tid = threadIdx.x;
    const int warp = tid >> 5, lane = tid & 31;
    const int img = blockIdx.y, tile = blockIdx.x;
    const int r0 = tile * 8 - 4;
    const int col = warp * 128 + lane * 4;
    const float BND = IS_MIN ? __int_as_float(0x7F800000) : __int_as_float(0xFF800000);
    const float* s = src + (size_t)img * NPIX;
    float* dp = dst + (size_t)img * NPIX;

    float4 d[16];
#pragma unroll
    for (int i = 0; i < 16; i++) {
        int rr = r0 + i;
        if (rr >= 0 && rr < IMG) d[i] = *(const float4*)(s + (size_t)rr * IMG + col);
        else                     d[i] = make_float4(BND, BND, BND, BND);
    }

#pragma unroll
    for (int it = 0; it < 4; it++) {
        const int p = it & 1;
        if (lane == 0) {
#pragma unroll
            for (int i = 0; i < 16; i++) eL[((p * 4) + warp) * 16 + i] = d[i].x;
        } else if (lane == 31) {
#pragma unroll
            for (int i = 0; i < 16; i++) eR[((p * 4) + warp) * 16 + i] = d[i].w;
        }
        __syncthreads();

        const int lo = it + 1, hi = 14 - it;
        float4 hp = hrow<IS_MIN>(d[lo - 1], lo - 1, p, warp, lane, eL, eR, BND);
        float4 hc = hrow<IS_MIN>(d[lo],     lo,     p, warp, lane, eL, eR, BND);
#pragma unroll
        for (int r = lo; r <= hi; r++) {
            float4 hn = hrow<IS_MIN>(d[r + 1], r + 1, p, warp, lane, eL, eR, BND);
            if (IS_MIN) {
                d[r].x += fmin3(hp.x, hc.x, hn.x); d[r].y += fmin3(hp.y, hc.y, hn.y);
                d[r].z += fmin3(hp.z, hc.z, hn.z); d[r].w += fmin3(hp.w, hc.w, hn.w);
            } else {
                d[r].x += fmax3(hp.x, hc.x, hn.x); d[r].y += fmax3(hp.y, hc.y, hn.y);
                d[r].z += fmax3(hp.z, hc.z, hn.z); d[r].w += fmax3(hp.w, hc.w, hn.w);
            }
            hp = hc; hc = hn;
        }
    }

#pragma unroll
    for (int i = 4; i < 12; i++) {
        int rr = r0 + i;  // always in [0,511]
        *(float4*)(dp + (size_t)rr * IMG + col) = d[i];
    }
}

__global__ __launch_bounds__(128) void round_kernel(const float* __restrict__ srcMin,
                                                    const float* __restrict__ srcMax,
                                                    float* __restrict__ dstMin,
                                                    float* __restrict__ dstMax) {
    __shared__ float eL[2 * 4 * 16];
    __shared__ float eR[2 * 4 * 16];
    if (blockIdx.z == 0) do_round<true>(srcMin, dstMin, eL, eR);
    else                 do_round<false>(srcMax, dstMax, eL, eR);
}

// ---- head fast path: 2x4 pixels/thread, packed fma.rn.f32x2 ----------------
__global__ __launch_bounds__(128) void head_main_kernel(const float* __restrict__ gmin,
                                                        const float* __restrict__ gmax,
                                                        float* __restrict__ out) {
    __shared__ unsigned long long A2s[32][18];
    __shared__ unsigned long long cb2s[32];
    __shared__ float w2s[32];
    const int tid = threadIdx.y * 32 + threadIdx.x;
    {
        const unsigned long long* A2g = (const unsigned long long*)(&HC.A2[0][0][0]);
        for (int i = tid; i < 32 * 18; i += 128) ((unsigned long long*)A2s)[i] = A2g[i];
        if (tid < 32) {
            cb2s[tid] = ((const unsigned long long*)HC.cb2)[tid];
            w2s[tid] = HC.w2[tid];
        }
    }
    __syncthreads();

    const int img = blockIdx.z;
    const int x0 = (blockIdx.x * 32 + threadIdx.x) * 2;
    const int y0 = (blockIdx.y * 4 + threadIdx.y) * 4;
    const float* gm = gmin + (size_t)img * NPIX;
    const float* gx = gmax + (size_t)img * NPIX;
    const int xm2 = max(x0 - 2, 0);
    const int xp2 = min(x0 + 2, IMG - 2);

    unsigned long long tmin[6][3], tmax[6][3];
#pragma unroll
    for (int rr = 0; rr < 6; rr++) {
        int row = min(max(y0 + rr - 1, 0), IMG - 1);
        const float* pm = gm + (size_t)row * IMG;
        float2 L = *(const float2*)(pm + xm2);
        float2 M = *(const float2*)(pm + x0);
        float2 R = *(const float2*)(pm + xp2);
        tmin[rr][0] = pk2(L.y, M.x); tmin[rr][1] = pk2(M.x, M.y); tmin[rr][2] = pk2(M.y, R.x);
        const float* px = gx + (size_t)row * IMG;
        L = *(const float2*)(px + xm2);
        M = *(const float2*)(px + x0);
        R = *(const float2*)(px + xp2);
        tmax[rr][0] = pk2(L.y, M.x); tmax[rr][1] = pk2(M.x, M.y); tmax[rr][2] = pk2(M.y, R.x);
    }

    float accx[4] = {0.f, 0.f, 0.f, 0.f};
    float accy[4] = {0.f, 0.f, 0.f, 0.f};
#pragma unroll 2
    for (int j = 0; j < 32; j++) {
        unsigned long long u0 = cb2s[j], u1 = u0, u2 = u0, u3 = u0;
#pragma unroll
        for (int k = 0; k < 9; k++) {
            const int kh = k / 3, kw = k % 3;
            unsigned long long a = A2s[j][k];
            u0 = fma2(a, tmin[0 + kh][kw], u0);
            u1 = fma2(a, tmin[1 + kh][kw], u1);
            u2 = fma2(a, tmin[2 + kh][kw], u2);
            u3 = fma2(a, tmin[3 + kh][kw], u3);
        }
#pragma unroll
        for (int k = 0; k < 9; k++) {
            const int kh = k / 3, kw = k % 3;
            unsigned long long a = A2s[j][9 + k];
            u0 = fma2(a, tmax[0 + kh][kw], u0);
            u1 = fma2(a, tmax[1 + kh][kw], u1);
            u2 = fma2(a, tmax[2 + kh][kw], u2);
            u3 = fma2(a, tmax[3 + kh][kw], u3);
        }
        float w = w2s[j], lo, hi;
        upk2(u0, lo, hi);
        accx[0] = fmaf(w, fmaxf(lo, 0.f), accx[0]); accy[0] = fmaf(w, fmaxf(hi, 0.f), accy[0]);
        upk2(u1, lo, hi);
        accx[1] = fmaf(w, fmaxf(lo, 0.f), accx[1]); accy[1] = fmaf(w, fmaxf(hi, 0.f), accy[1]);
        upk2(u2, lo, hi);
        accx[2] = fmaf(w, fmaxf(lo, 0.f), accx[2]); accy[2] = fmaf(w, fmaxf(hi, 0.f), accy[2]);
        upk2(u3, lo, hi);
        accx[3] = fmaf(w, fmaxf(lo, 0.f), accx[3]); accy[3] = fmaf(w, fmaxf(hi, 0.f), accy[3]);
    }

    const float b2v = HC.b2;
#pragma unroll
    for (int i = 0; i < 4; i++) {
        float2 o;
        o.x = b2v + accx[i];
        o.y = b2v + accy[i];
        *(float2*)(out + (size_t)img * NPIX + (size_t)(y0 + i) * IMG + x0) = o;
    }
}

// ---- head border: exact tap-gated recompute for the 1-pixel frame ----------
__global__ void head_border_kernel(const float* __restrict__ gmin,
                                   const float* __restrict__ gmax,
                                   float* __restrict__ out) {
    const int img = blockIdx.y;
    const int bi = blockIdx.x * blockDim.x + threadIdx.x;  // 0..2043
    if (bi >= 2044) return;
    int x, y;
    if (bi < 512)        { y = 0;   x = bi; }
    else if (bi < 1024)  { y = 511; x = bi - 512; }
    else if (bi < 1534)  { x = 0;   y = bi - 1024 + 1; }
    else                 { x = 511; y = bi - 1534 + 1; }

    const float* gm = gmin + (size_t)img * NPIX;
    const float* gx = gmax + (size_t)img * NPIX;

    float vmn[9], vmx[9];
    bool valid[9];
#pragma unroll
    for (int k = 0; k < 9; k++) {
        int ty = y + k / 3 - 1, tx = x + k % 3 - 1;
        valid[k] = (ty >= 0 && ty < IMG && tx >= 0 && tx < IMG);
        size_t off = (size_t)min(max(ty, 0), IMG - 1) * IMG + (size_t)min(max(tx, 0), IMG - 1);
        vmn[k] = valid[k] ? gm[off] : 0.f;
        vmx[k] = valid[k] ? gx[off] : 0.f;
    }
    float acc = 0.f;
    for (int j = 0; j < 32; j++) {
        float u = HC.b1[j];
#pragma unroll
        for (int k = 0; k < 9; k++) {
            if (valid[k])
                u += HC.Amin[j][k] * vmn[k] + HC.Amax[j][k] * vmx[k] + HC.Bsum[j][k];
        }
        acc = fmaf(HC.w2[j], fmaxf(u, 0.f), acc);
    }
    out[(size_t)img * NPIX + (size_t)y * IMG + x] = HC.b2 + acc;
}

// ---------------------------------------------------------------------------
extern "C" void kernel_launch(void* const* d_in, const int* in_sizes, int n_in,
                              void* d_out, int out_size) {
    const float* x  = (const float*)d_in[0];
    const float* w0 = (const float*)d_in[1];
    const float* b0 = (const float*)d_in[2];
    const float* w1 = (const float*)d_in[3];
    const float* b1 = (const float*)d_in[4];
    const float* w2 = (const float*)d_in[5];
    const float* b2 = (const float*)d_in[6];
    float* out = (float*)d_out;

    prep_kernel<<<1, 288>>>(w0, b0, w1, b1, w2, b2);

    // Resolve device-global addresses host-side (cudaGetSymbolAddress not
    // needed: use a tiny helper via cudaMemcpyFromSymbol-free path).
    // We can take addresses directly in device code only, so obtain them via
    // cudaGetSymbolAddress (allowed: no allocation).
    static float *pMinA = nullptr, *pMinB = nullptr, *pMaxA = nullptr, *pMaxB = nullptr;
    if (!pMinA) {
        cudaGetSymbolAddress((void**)&pMinA, g_min_a);
        cudaGetSymbolAddress((void**)&pMinB, g_min_b);
        cudaGetSymbolAddress((void**)&pMaxA, g_max_a);
        cudaGetSymbolAddress((void**)&pMaxB, g_max_b);
    }

    dim3 rblk(128);
    dim3 rgrd(IMG / 8, NIMG, 2);
    // 16 pooling iterations = 4 fused rounds of 4.
    round_kernel<<<rgrd, rblk>>>(x,     x,     pMinA, pMaxA);
    round_kernel<<<rgrd, rblk>>>(pMinA, pMaxA, pMinB, pMaxB);
    round_kernel<<<rgrd, rblk>>>(pMinB, pMaxB, pMinA, pMaxA);
    round_kernel<<<rgrd, rblk>>>(pMinA, pMaxA, pMinB, pMaxB);

    dim3 hblk(32, 4);
    dim3 hgrd(IMG / 64, IMG / 16, NIMG);
    head_main_kernel<<<hgrd, hblk>>>(pMinB, pMaxB, out);

    head_border_kernel<<<dim3(16, NIMG), 128>>>(pMinB, pMaxB, out);
}